// round 14
// baseline (speedup 1.0000x reference)
#include <cuda_runtime.h>
#include <cuda_bf16.h>
#include <cuda_fp16.h>
#include <math.h>
#include <stdint.h>

#define NTOK 4096
#define D 1024
#define H 4096
#define NE 8
#define KSTG 16384            // one stage, one matrix: 128 rows * 128B (64 bf16, SW128)
#define GEMM_SMEM (6 * KSTG)  // 3 stages * (A+B) = 96KB

__device__ double d_wsum[17];
__device__ float  d_wscale[17];
__device__ float  d_gwqf[NE * D];
__device__ __nv_bfloat16 d_w1q[(size_t)NE * H * D];
__device__ __nv_bfloat16 d_w2q[(size_t)NE * D * H];
__device__ __nv_bfloat16 d_qx[(size_t)NTOK * D];
__device__ float d_sx[NTOK];
__device__ float d_gates[NTOK * NE];
__device__ float d_abuf[(size_t)NTOK * NE * H];   // gemm1 gelu out (fp32)
__device__ __nv_bfloat16 d_qa[(size_t)NTOK * NE * H];
__device__ float d_sa[NTOK * NE];
__device__ __half d_obuf[(size_t)NTOK * NE * D];  // gemm2 per-expert contributions (fp16)

__device__ __forceinline__ uint32_t smem_u32(const void* p) {
    uint32_t a;
    asm("{ .reg .u64 t; cvta.to.shared.u64 t, %1; cvt.u32.u64 %0, t; }" : "=r"(a) : "l"(p));
    return a;
}
__device__ __forceinline__ void cp16(uint32_t dst, const void* src) {
    asm volatile("cp.async.cg.shared.global [%0], [%1], 16;" :: "r"(dst), "l"(src));
}
#define CP_COMMIT() asm volatile("cp.async.commit_group;" ::: "memory")
#define CP_WAIT1()  asm volatile("cp.async.wait_group 1;" ::: "memory")

__device__ __forceinline__ void mma16816(float* d, const uint32_t* a, const uint32_t* b) {
    asm volatile(
        "mma.sync.aligned.m16n8k16.row.col.f32.bf16.bf16.f32 "
        "{%0,%1,%2,%3}, {%4,%5,%6,%7}, {%8,%9}, {%0,%1,%2,%3};\n"
        : "+f"(d[0]), "+f"(d[1]), "+f"(d[2]), "+f"(d[3])
        : "r"(a[0]), "r"(a[1]), "r"(a[2]), "r"(a[3]), "r"(b[0]), "r"(b[1]));
}
__device__ __forceinline__ void ldsm4(uint32_t* r, uint32_t addr) {
    asm volatile("ldmatrix.sync.aligned.m8n8.x4.shared.b16 {%0,%1,%2,%3}, [%4];"
                 : "=r"(r[0]), "=r"(r[1]), "=r"(r[2]), "=r"(r[3]) : "r"(addr));
}
// A&S 7.1.26 erf (|err| < 1.5e-7) -> exact-class gelu
__device__ __forceinline__ float gelu_exact(float h) {
    const float u = 0.70710678118654752440f * h;
    const float au = fabsf(u);
    const float t = __fdividef(1.0f, fmaf(0.3275911f, au, 1.0f));
    float p = fmaf(1.061405429f, t, -1.453152027f);
    p = fmaf(p, t, 1.421413741f);
    p = fmaf(p, t, -0.284496736f);
    p = fmaf(p, t, 0.254829592f);
    p *= t;
    const float e = __expf(-au * au);
    const float erfa = fmaf(-p, e, 1.0f);
    const float er = copysignf(erfa, u);
    return 0.5f * h * (1.0f + er);
}
__device__ __forceinline__ uint2 packbf4(float q0, float q1, float q2, float q3) {
    uint2 u;
    u.x = (uint32_t)__bfloat16_as_ushort(__float2bfloat16(q0)) |
          ((uint32_t)__bfloat16_as_ushort(__float2bfloat16(q1)) << 16);
    u.y = (uint32_t)__bfloat16_as_ushort(__float2bfloat16(q2)) |
          ((uint32_t)__bfloat16_as_ushort(__float2bfloat16(q3)) << 16);
    return u;
}

// ---------------- prep kernels ----------------
__global__ void k_init() { if (threadIdx.x < 17) d_wsum[threadIdx.x] = 0.0; }

__global__ void __launch_bounds__(256) k_abs_sum(const float* __restrict__ w, int slot0, size_t n_per) {
    __shared__ double sd[8];
    const size_t n4 = n_per >> 2;
    const float4* w4 = (const float4*)(w + (size_t)blockIdx.y * n_per);
    float s = 0.f;
    for (size_t i = (size_t)blockIdx.x * 256 + threadIdx.x; i < n4; i += (size_t)gridDim.x * 256) {
        float4 v = w4[i];
        s += fabsf(v.x) + fabsf(v.y) + fabsf(v.z) + fabsf(v.w);
    }
    double sdv = (double)s;
    for (int o = 16; o; o >>= 1) sdv += __shfl_xor_sync(0xffffffffu, sdv, o);
    if ((threadIdx.x & 31) == 0) sd[threadIdx.x >> 5] = sdv;
    __syncthreads();
    if (threadIdx.x == 0) {
        double t = 0;
        for (int i = 0; i < 8; i++) t += sd[i];
        atomicAdd(&d_wsum[slot0 + blockIdx.y], t);
    }
}

__global__ void k_finalize() {
    int i = threadIdx.x;
    if (i < 17) {
        double cnt = (i == 0) ? (double)(NE * D) : (double)H * (double)D;
        d_wscale[i] = 1.0f / fmaxf((float)(d_wsum[i] / cnt), 1e-5f);
    }
}

__global__ void __launch_bounds__(256) k_quant_w(const float* __restrict__ w, int which,
                                                 int slot0, size_t n_per) {
    __nv_bfloat16* q = (which == 1) ? d_w1q : d_w2q;
    const int e = blockIdx.y;
    const float s = d_wscale[slot0 + e];
    const size_t base = (size_t)e * n_per;
    const float4* w4 = (const float4*)(w + base);
    uint2* q4 = (uint2*)(q + base);
    const size_t n4 = n_per >> 2;
    for (size_t i = (size_t)blockIdx.x * 256 + threadIdx.x; i < n4; i += (size_t)gridDim.x * 256) {
        float4 v = w4[i];
        q4[i] = packbf4(fminf(fmaxf(rintf(v.x * s), -1.f), 1.f),
                        fminf(fmaxf(rintf(v.y * s), -1.f), 1.f),
                        fminf(fmaxf(rintf(v.z * s), -1.f), 1.f),
                        fminf(fmaxf(rintf(v.w * s), -1.f), 1.f));
    }
}

__global__ void __launch_bounds__(256) k_quant_gw(const float* __restrict__ gw) {
    const float s = d_wscale[0];
    for (int i = blockIdx.x * 256 + threadIdx.x; i < NE * D; i += gridDim.x * 256)
        d_gwqf[i] = fminf(fmaxf(rintf(gw[i] * s), -1.f), 1.f);
}

// per-token rmsnorm + quant + gate softmax
__global__ void __launch_bounds__(256) k_xquant(const float* __restrict__ x,
                                                const float* __restrict__ gb) {
    const int t = blockIdx.x;
    const int tid = threadIdx.x;
    __shared__ float sq[D];
    __shared__ float wred[16], red2[2], slog[NE];
    float4 v = ((const float4*)(x + (size_t)t * D))[tid];
    float ss = v.x * v.x + v.y * v.y + v.z * v.z + v.w * v.w;
    float am = fmaxf(fmaxf(fabsf(v.x), fabsf(v.y)), fmaxf(fabsf(v.z), fabsf(v.w)));
    for (int o = 16; o; o >>= 1) {
        ss += __shfl_xor_sync(0xffffffffu, ss, o);
        am = fmaxf(am, __shfl_xor_sync(0xffffffffu, am, o));
    }
    if ((tid & 31) == 0) { wred[tid >> 5] = ss; wred[8 + (tid >> 5)] = am; }
    __syncthreads();
    if (tid == 0) {
        float S = 0.f, A = 0.f;
        for (int i = 0; i < 8; i++) { S += wred[i]; A = fmaxf(A, wred[8 + i]); }
        red2[0] = S; red2[1] = A;
    }
    __syncthreads();
    const float nrm = fmaxf(sqrtf(red2[0]), 1e-12f);
    const float scale = 127.0f / fmaxf(red2[1] / nrm * 32.0f, 1e-5f);
    const float m = 32.0f / nrm * scale;
    float q0 = fminf(fmaxf(rintf(v.x * m), -128.f), 127.f);
    float q1 = fminf(fmaxf(rintf(v.y * m), -128.f), 127.f);
    float q2 = fminf(fmaxf(rintf(v.z * m), -128.f), 127.f);
    float q3 = fminf(fmaxf(rintf(v.w * m), -128.f), 127.f);
    sq[tid * 4 + 0] = q0; sq[tid * 4 + 1] = q1; sq[tid * 4 + 2] = q2; sq[tid * 4 + 3] = q3;
    ((uint2*)d_qx)[t * 256 + tid] = packbf4(q0, q1, q2, q3);
    if (tid == 0) d_sx[t] = scale;
    __syncthreads();
    const int w = tid >> 5, l = tid & 31;
    float acc = 0.f;
    for (int i = l; i < D; i += 32) acc += sq[i] * d_gwqf[w * D + i];
    for (int o = 16; o; o >>= 1) acc += __shfl_xor_sync(0xffffffffu, acc, o);
    if (l == 0) slog[w] = acc;
    __syncthreads();
    if (tid == 0) {
        float inv = 1.0f / (scale * d_wscale[0]);
        float lg[NE], mx = -1e30f;
        for (int e = 0; e < NE; e++) { lg[e] = slog[e] * inv + gb[e]; mx = fmaxf(mx, lg[e]); }
        float se = 0.f;
        for (int e = 0; e < NE; e++) { lg[e] = expf(lg[e] - mx); se += lg[e]; }
        for (int e = 0; e < NE; e++) d_gates[t * NE + e] = lg[e] / se;
    }
}

// ------- bf16 GEMM core: BM=128 BN=128 BK=64, 128 threads, warp tile 64x64 (2x2 warps),
//         SW128 swizzle, 3-stage cp.async, 2 CTAs/SM. Crossbar bytes/MAC cut 25% vs 32x64.
struct Frag { float c[4][8][4]; };

__device__ __forceinline__ void g_fill(uint32_t sA, uint32_t sB, int st,
                                       const __nv_bfloat16* Ag, size_t lda,
                                       const __nv_bfloat16* Bg, size_t ldb, int k0, int tid) {
#pragma unroll
    for (int h = 0; h < 8; h++) {
        const int idx = tid + h * 128;
        const int row = idx >> 3, ch = idx & 7;
        const uint32_t off = (uint32_t)row * 128 + (uint32_t)((ch ^ (row & 7)) << 4);
        cp16(sA + (uint32_t)st * KSTG + off, Ag + (size_t)row * lda + k0 + ch * 8);
        cp16(sB + (uint32_t)st * KSTG + off, Bg + (size_t)row * ldb + k0 + ch * 8);
    }
}

__device__ __forceinline__ void g_compute(uint32_t aSt, uint32_t bSt,
                                          const uint32_t* pbA, const uint32_t* hiA,
                                          const uint32_t* pbB, const uint32_t* hiB,
                                          Frag& f) {
#pragma unroll
    for (int ks = 0; ks < 4; ks++) {
        uint32_t af[4][4], bf[8][2], t[4];
#pragma unroll
        for (int mf = 0; mf < 4; mf++)
            ldsm4(af[mf], aSt + pbA[mf] + ((((uint32_t)ks) ^ hiA[mf]) << 5));
#pragma unroll
        for (int np = 0; np < 4; np++) {
            ldsm4(t, bSt + pbB[np] + ((((uint32_t)ks) ^ hiB[np]) << 5));
            bf[np * 2][0] = t[0]; bf[np * 2][1] = t[1];
            bf[np * 2 + 1][0] = t[2]; bf[np * 2 + 1][1] = t[3];
        }
#pragma unroll
        for (int mf = 0; mf < 4; mf++)
#pragma unroll
            for (int nf = 0; nf < 8; nf++) mma16816(f.c[mf][nf], af[mf], bf[nf]);
    }
}

#define GEMM_BODY(Ag, LDA, Bg, LDB, KT)                                        \
    extern __shared__ __align__(16) char smem[];                              \
    const uint32_t sA = smem_u32(smem), sB = sA + 3 * KSTG;                   \
    const int tid = threadIdx.x;                                              \
    const int warp = tid >> 5, lane = tid & 31;                               \
    const int wm = warp >> 1, wn = warp & 1;                                  \
    const int g = lane >> 2, tq = lane & 3;                                   \
    uint32_t pbA[4], hiA[4], pbB[4], hiB[4];                                  \
    {                                                                         \
        const uint32_t hbA = ((uint32_t)lane >> 4) & 1u;                      \
        _Pragma("unroll")                                                     \
        for (int mf = 0; mf < 4; mf++) {                                      \
            const uint32_t r = (uint32_t)(wm * 64 + mf * 16) + ((uint32_t)lane & 15u); \
            pbA[mf] = r * 128u + ((hbA ^ (r & 1u)) << 4);                     \
            hiA[mf] = (r >> 1) & 3u;                                          \
        }                                                                     \
        const uint32_t hbB = ((uint32_t)lane >> 3) & 1u;                      \
        _Pragma("unroll")                                                     \
        for (int np = 0; np < 4; np++) {                                      \
            const uint32_t r = (uint32_t)(wn * 64 + np * 16) + ((uint32_t)lane & 7u) + \
                               ((((uint32_t)lane >> 4) & 1u) << 3);           \
            pbB[np] = r * 128u + ((hbB ^ (r & 1u)) << 4);                     \
            hiB[np] = (r >> 1) & 3u;                                          \
        }                                                                     \
    }                                                                         \
    Frag f;                                                                   \
    for (int i = 0; i < 4; i++)                                               \
        for (int j = 0; j < 8; j++)                                           \
            for (int k = 0; k < 4; k++) f.c[i][j][k] = 0.f;                   \
    g_fill(sA, sB, 0, Ag, LDA, Bg, LDB, 0, tid); CP_COMMIT();                 \
    g_fill(sA, sB, 1, Ag, LDA, Bg, LDB, 64, tid); CP_COMMIT();                \
    int cur = 0, nxt = 2;                                                     \
    for (int kt = 0; kt < (KT); kt++) {                                       \
        CP_WAIT1();                                                           \
        __syncthreads();                                                      \
        g_compute(sA + (uint32_t)cur * KSTG, sB + (uint32_t)cur * KSTG,       \
                  pbA, hiA, pbB, hiB, f);                                     \
        if (kt + 2 < (KT)) g_fill(sA, sB, nxt, Ag, LDA, Bg, LDB, (kt + 2) * 64, tid); \
        CP_COMMIT();                                                          \
        cur = (cur == 2) ? 0 : cur + 1;                                       \
        nxt = (nxt == 2) ? 0 : nxt + 1;                                       \
    }

// GEMM1: qx[4096,1024] @ w1q[e][H,1024]^T -> gelu -> abuf
__global__ void __launch_bounds__(128, 2) k_gemm1(const float* __restrict__ b1) {
    const int e = blockIdx.z;
    const __nv_bfloat16* Agp = d_qx + (size_t)blockIdx.x * 128 * D;
    const __nv_bfloat16* Bgp = d_w1q + ((size_t)e * H + (size_t)blockIdx.y * 128) * D;
    GEMM_BODY(Agp, D, Bgp, D, D / 64)

    const float sw1 = d_wscale[1 + e];
#pragma unroll
    for (int mf = 0; mf < 4; mf++) {
        const int r0 = blockIdx.x * 128 + wm * 64 + mf * 16 + g;
        const float i0 = 1.0f / (d_sx[r0] * sw1);
        const float i1 = 1.0f / (d_sx[r0 + 8] * sw1);
#pragma unroll
        for (int nf = 0; nf < 8; nf++) {
            const int col = blockIdx.y * 128 + wn * 64 + nf * 8 + tq * 2;
            const float bb0 = b1[e * H + col], bb1 = b1[e * H + col + 1];
            float2 o0, o1;
            o0.x = gelu_exact(f.c[mf][nf][0] * i0 + bb0);
            o0.y = gelu_exact(f.c[mf][nf][1] * i0 + bb1);
            o1.x = gelu_exact(f.c[mf][nf][2] * i1 + bb0);
            o1.y = gelu_exact(f.c[mf][nf][3] * i1 + bb1);
            *(float2*)(&d_abuf[((size_t)r0 * NE + e) * H + col]) = o0;
            *(float2*)(&d_abuf[((size_t)(r0 + 8) * NE + e) * H + col]) = o1;
        }
    }
}

// per-(token,expert) rmsnorm + quant
__global__ void __launch_bounds__(256) k_aquant() {
    const size_t r = blockIdx.x;
    const float4* a = (const float4*)(d_abuf + r * (size_t)H);
    __shared__ float wss[8], wam[8], red2[2];
    const int tid = threadIdx.x;
    float4 v[4];
    float ss = 0.f, am = 0.f;
#pragma unroll
    for (int i = 0; i < 4; i++) {
        v[i] = a[tid + i * 256];
        ss += v[i].x * v[i].x + v[i].y * v[i].y + v[i].z * v[i].z + v[i].w * v[i].w;
        am = fmaxf(am, fmaxf(fmaxf(fabsf(v[i].x), fabsf(v[i].y)),
                             fmaxf(fabsf(v[i].z), fabsf(v[i].w))));
    }
    for (int o = 16; o; o >>= 1) {
        ss += __shfl_xor_sync(0xffffffffu, ss, o);
        am = fmaxf(am, __shfl_xor_sync(0xffffffffu, am, o));
    }
    if ((tid & 31) == 0) { wss[tid >> 5] = ss; wam[tid >> 5] = am; }
    __syncthreads();
    if (tid == 0) {
        float S = 0.f, A = 0.f;
        for (int i = 0; i < 8; i++) { S += wss[i]; A = fmaxf(A, wam[i]); }
        red2[0] = S; red2[1] = A;
    }
    __syncthreads();
    const float nrm = fmaxf(sqrtf(red2[0]), 1e-12f);
    const float scale = 127.0f / fmaxf(red2[1] / nrm * 64.0f, 1e-5f);
    if (tid == 0) d_sa[r] = scale;
    const float m = 64.0f / nrm * scale;
    uint2* qo = (uint2*)(d_qa + r * (size_t)H);
#pragma unroll
    for (int i = 0; i < 4; i++) {
        qo[tid + i * 256] = packbf4(fminf(fmaxf(rintf(v[i].x * m), -128.f), 127.f),
                                    fminf(fmaxf(rintf(v[i].y * m), -128.f), 127.f),
                                    fminf(fmaxf(rintf(v[i].z * m), -128.f), 127.f),
                                    fminf(fmaxf(rintf(v[i].w * m), -128.f), 127.f));
    }
}

// GEMM2: per expert qa @ w2q^T -> gate*(c*inv+b2) -> fp16 scratch d_obuf
__global__ void __launch_bounds__(128, 2) k_gemm2(const float* __restrict__ b2) {
    const int e = blockIdx.z;
    const __nv_bfloat16* Agp = d_qa + ((size_t)blockIdx.x * 128 * NE + e) * (size_t)H;
    const __nv_bfloat16* Bgp = d_w2q + ((size_t)e * D + (size_t)blockIdx.y * 128) * H;
    GEMM_BODY(Agp, (size_t)NE * H, Bgp, H, H / 64)

    const float sw2 = d_wscale[9 + e];
#pragma unroll
    for (int mf = 0; mf < 4; mf++) {
        const int r0 = blockIdx.x * 128 + wm * 64 + mf * 16 + g;
        const float g0 = d_gates[r0 * NE + e], g1 = d_gates[(r0 + 8) * NE + e];
        const float i0 = 1.0f / (d_sa[r0 * NE + e] * sw2);
        const float i1 = 1.0f / (d_sa[(r0 + 8) * NE + e] * sw2);
#pragma unroll
        for (int nf = 0; nf < 8; nf++) {
            const int col = blockIdx.y * 128 + wn * 64 + nf * 8 + tq * 2;
            const float bb0 = b2[e * D + col], bb1 = b2[e * D + col + 1];
            __half2 h0 = __floats2half2_rn(g0 * (f.c[mf][nf][0] * i0 + bb0),
                                           g0 * (f.c[mf][nf][1] * i0 + bb1));
            __half2 h1 = __floats2half2_rn(g1 * (f.c[mf][nf][2] * i1 + bb0),
                                           g1 * (f.c[mf][nf][3] * i1 + bb1));
            *(__half2*)(&d_obuf[((size_t)r0 * NE + e) * D + col]) = h0;
            *(__half2*)(&d_obuf[((size_t)(r0 + 8) * NE + e) * D + col]) = h1;
        }
    }
}

// final reduce over experts: read fp16 scratch, accumulate fp32, write out
__global__ void __launch_bounds__(256) k_reduce(float* __restrict__ out) {
    const size_t i8 = (size_t)blockIdx.x * 256 + threadIdx.x;   // < NTOK*D/8
    const int t = (int)(i8 >> 7), d8 = (int)(i8 & 127);
    float s[8] = {0.f, 0.f, 0.f, 0.f, 0.f, 0.f, 0.f, 0.f};
#pragma unroll
    for (int e = 0; e < NE; e++) {
        const __half2* p = (const __half2*)(d_obuf + (((size_t)t * NE + e) << 10)) + d8 * 4;
#pragma unroll
        for (int j = 0; j < 4; j++) {
            float2 v = __half22float2(p[j]);
            s[j * 2] += v.x; s[j * 2 + 1] += v.y;
        }
    }
    float4* o4 = (float4*)(out + ((size_t)t << 10) + d8 * 8);
    o4[0] = make_float4(s[0], s[1], s[2], s[3]);
    o4[1] = make_float4(s[4], s[5], s[6], s[7]);
}

extern "C" void kernel_launch(void* const* d_in, const int* in_sizes, int n_in,
                              void* d_out, int out_size) {
    const float* x  = (const float*)d_in[0];
    const float* gw = (const float*)d_in[1];
    const float* gb = (const float*)d_in[2];
    const float* w1 = (const float*)d_in[3];
    const float* b1 = (const float*)d_in[4];
    const float* w2 = (const float*)d_in[5];
    const float* b2 = (const float*)d_in[6];
    float* out = (float*)d_out;

    cudaFuncSetAttribute(k_gemm1, cudaFuncAttributeMaxDynamicSharedMemorySize, GEMM_SMEM);
    cudaFuncSetAttribute(k_gemm2, cudaFuncAttributeMaxDynamicSharedMemorySize, GEMM_SMEM);

    k_init<<<1, 32>>>();
    k_abs_sum<<<dim3(8, 1), 256>>>(gw, 0, (size_t)NE * D);
    k_abs_sum<<<dim3(128, NE), 256>>>(w1, 1, (size_t)H * D);
    k_abs_sum<<<dim3(128, NE), 256>>>(w2, 9, (size_t)H * D);
    k_finalize<<<1, 32>>>();
    k_quant_gw<<<8, 256>>>(gw);
    k_quant_w<<<dim3(128, NE), 256>>>(w1, 1, 1, (size_t)H * D);
    k_quant_w<<<dim3(128, NE), 256>>>(w2, 2, 9, (size_t)H * D);
    k_xquant<<<NTOK, 256>>>(x, gb);
    k_gemm1<<<dim3(NTOK / 128, H / 128, NE), 128, GEMM_SMEM>>>(b1);
    k_aquant<<<NTOK * NE, 256>>>();
    k_gemm2<<<dim3(NTOK / 128, D / 128, NE), 128, GEMM_SMEM>>>(b2);
    k_reduce<<<(NTOK * D) / 2048, 256>>>(out);
}

// round 15
// speedup vs baseline: 1.0303x; 1.0303x over previous
#include <cuda_runtime.h>
#include <cuda_bf16.h>
#include <cuda_fp16.h>
#include <math.h>
#include <stdint.h>

#define NTOK 4096
#define D 1024
#define H 4096
#define NE 8
#define KSTG 16384            // one stage, one matrix: 128 rows * 128B (64 bf16, SW128)
#define GEMM_SMEM (6 * KSTG)  // 3 stages * (A+B) = 96KB

__device__ double d_wsum[17];
__device__ float  d_wscale[17];
__device__ float  d_gwqf[NE * D];
__device__ __nv_bfloat16 d_w1q[(size_t)NE * H * D];
__device__ __nv_bfloat16 d_w2q[(size_t)NE * D * H];
__device__ __nv_bfloat16 d_qx[(size_t)NTOK * D];
__device__ float d_sx[NTOK];
__device__ float d_gates[NTOK * NE];
__device__ float d_abuf[(size_t)NTOK * NE * H];   // gemm1 gelu out (fp32)
__device__ __nv_bfloat16 d_qa[(size_t)NTOK * NE * H];
__device__ float d_sa[NTOK * NE];
__device__ __half d_obuf[(size_t)NTOK * NE * D];  // gemm2 per-expert contributions (fp16)

__device__ __forceinline__ uint32_t smem_u32(const void* p) {
    uint32_t a;
    asm("{ .reg .u64 t; cvta.to.shared.u64 t, %1; cvt.u32.u64 %0, t; }" : "=r"(a) : "l"(p));
    return a;
}
__device__ __forceinline__ void cp16(uint32_t dst, const void* src) {
    asm volatile("cp.async.cg.shared.global [%0], [%1], 16;" :: "r"(dst), "l"(src));
}
#define CP_COMMIT() asm volatile("cp.async.commit_group;" ::: "memory")
#define CP_WAIT1()  asm volatile("cp.async.wait_group 1;" ::: "memory")

__device__ __forceinline__ void mma16816(float* d, const uint32_t* a, const uint32_t* b) {
    asm volatile(
        "mma.sync.aligned.m16n8k16.row.col.f32.bf16.bf16.f32 "
        "{%0,%1,%2,%3}, {%4,%5,%6,%7}, {%8,%9}, {%0,%1,%2,%3};\n"
        : "+f"(d[0]), "+f"(d[1]), "+f"(d[2]), "+f"(d[3])
        : "r"(a[0]), "r"(a[1]), "r"(a[2]), "r"(a[3]), "r"(b[0]), "r"(b[1]));
}
__device__ __forceinline__ void ldsm4(uint32_t* r, uint32_t addr) {
    asm volatile("ldmatrix.sync.aligned.m8n8.x4.shared.b16 {%0,%1,%2,%3}, [%4];"
                 : "=r"(r[0]), "=r"(r[1]), "=r"(r[2]), "=r"(r[3]) : "r"(addr));
}
// A&S 7.1.26 erf (|err| < 1.5e-7) -> exact-class gelu
__device__ __forceinline__ float gelu_exact(float h) {
    const float u = 0.70710678118654752440f * h;
    const float au = fabsf(u);
    const float t = __fdividef(1.0f, fmaf(0.3275911f, au, 1.0f));
    float p = fmaf(1.061405429f, t, -1.453152027f);
    p = fmaf(p, t, 1.421413741f);
    p = fmaf(p, t, -0.284496736f);
    p = fmaf(p, t, 0.254829592f);
    p *= t;
    const float e = __expf(-au * au);
    const float erfa = fmaf(-p, e, 1.0f);
    const float er = copysignf(erfa, u);
    return 0.5f * h * (1.0f + er);
}
__device__ __forceinline__ uint2 packbf4(float q0, float q1, float q2, float q3) {
    uint2 u;
    u.x = (uint32_t)__bfloat16_as_ushort(__float2bfloat16(q0)) |
          ((uint32_t)__bfloat16_as_ushort(__float2bfloat16(q1)) << 16);
    u.y = (uint32_t)__bfloat16_as_ushort(__float2bfloat16(q2)) |
          ((uint32_t)__bfloat16_as_ushort(__float2bfloat16(q3)) << 16);
    return u;
}

// ---------------- prep kernels ----------------
__global__ void k_init() { if (threadIdx.x < 17) d_wsum[threadIdx.x] = 0.0; }

__global__ void __launch_bounds__(256) k_abs_sum(const float* __restrict__ w, int slot0, size_t n_per) {
    __shared__ double sd[8];
    const size_t n4 = n_per >> 2;
    const float4* w4 = (const float4*)(w + (size_t)blockIdx.y * n_per);
    float s = 0.f;
    for (size_t i = (size_t)blockIdx.x * 256 + threadIdx.x; i < n4; i += (size_t)gridDim.x * 256) {
        float4 v = w4[i];
        s += fabsf(v.x) + fabsf(v.y) + fabsf(v.z) + fabsf(v.w);
    }
    double sdv = (double)s;
    for (int o = 16; o; o >>= 1) sdv += __shfl_xor_sync(0xffffffffu, sdv, o);
    if ((threadIdx.x & 31) == 0) sd[threadIdx.x >> 5] = sdv;
    __syncthreads();
    if (threadIdx.x == 0) {
        double t = 0;
        for (int i = 0; i < 8; i++) t += sd[i];
        atomicAdd(&d_wsum[slot0 + blockIdx.y], t);
    }
}

// finalize scales for slots [lo, hi)
__global__ void k_finalize(int lo, int hi) {
    int i = lo + threadIdx.x;
    if (i < hi) {
        double cnt = (i == 0) ? (double)(NE * D) : (double)H * (double)D;
        d_wscale[i] = 1.0f / fmaxf((float)(d_wsum[i] / cnt), 1e-5f);
    }
}

__global__ void __launch_bounds__(256) k_quant_w(const float* __restrict__ w, int which,
                                                 int slot0, size_t n_per) {
    __nv_bfloat16* q = (which == 1) ? d_w1q : d_w2q;
    const int e = blockIdx.y;
    const float s = d_wscale[slot0 + e];
    const size_t base = (size_t)e * n_per;
    const float4* w4 = (const float4*)(w + base);
    uint2* q4 = (uint2*)(q + base);
    const size_t n4 = n_per >> 2;
    for (size_t i = (size_t)blockIdx.x * 256 + threadIdx.x; i < n4; i += (size_t)gridDim.x * 256) {
        float4 v = w4[i];
        q4[i] = packbf4(fminf(fmaxf(rintf(v.x * s), -1.f), 1.f),
                        fminf(fmaxf(rintf(v.y * s), -1.f), 1.f),
                        fminf(fmaxf(rintf(v.z * s), -1.f), 1.f),
                        fminf(fmaxf(rintf(v.w * s), -1.f), 1.f));
    }
}

__global__ void __launch_bounds__(256) k_quant_gw(const float* __restrict__ gw) {
    const float s = d_wscale[0];
    for (int i = blockIdx.x * 256 + threadIdx.x; i < NE * D; i += gridDim.x * 256)
        d_gwqf[i] = fminf(fmaxf(rintf(gw[i] * s), -1.f), 1.f);
}

// per-token rmsnorm + quant + gate softmax
__global__ void __launch_bounds__(256) k_xquant(const float* __restrict__ x,
                                                const float* __restrict__ gb) {
    const int t = blockIdx.x;
    const int tid = threadIdx.x;
    __shared__ float sq[D];
    __shared__ float wred[16], red2[2], slog[NE];
    float4 v = ((const float4*)(x + (size_t)t * D))[tid];
    float ss = v.x * v.x + v.y * v.y + v.z * v.z + v.w * v.w;
    float am = fmaxf(fmaxf(fabsf(v.x), fabsf(v.y)), fmaxf(fabsf(v.z), fabsf(v.w)));
    for (int o = 16; o; o >>= 1) {
        ss += __shfl_xor_sync(0xffffffffu, ss, o);
        am = fmaxf(am, __shfl_xor_sync(0xffffffffu, am, o));
    }
    if ((tid & 31) == 0) { wred[tid >> 5] = ss; wred[8 + (tid >> 5)] = am; }
    __syncthreads();
    if (tid == 0) {
        float S = 0.f, A = 0.f;
        for (int i = 0; i < 8; i++) { S += wred[i]; A = fmaxf(A, wred[8 + i]); }
        red2[0] = S; red2[1] = A;
    }
    __syncthreads();
    const float nrm = fmaxf(sqrtf(red2[0]), 1e-12f);
    const float scale = 127.0f / fmaxf(red2[1] / nrm * 32.0f, 1e-5f);
    const float m = 32.0f / nrm * scale;
    float q0 = fminf(fmaxf(rintf(v.x * m), -128.f), 127.f);
    float q1 = fminf(fmaxf(rintf(v.y * m), -128.f), 127.f);
    float q2 = fminf(fmaxf(rintf(v.z * m), -128.f), 127.f);
    float q3 = fminf(fmaxf(rintf(v.w * m), -128.f), 127.f);
    sq[tid * 4 + 0] = q0; sq[tid * 4 + 1] = q1; sq[tid * 4 + 2] = q2; sq[tid * 4 + 3] = q3;
    ((uint2*)d_qx)[t * 256 + tid] = packbf4(q0, q1, q2, q3);
    if (tid == 0) d_sx[t] = scale;
    __syncthreads();
    const int w = tid >> 5, l = tid & 31;
    float acc = 0.f;
    for (int i = l; i < D; i += 32) acc += sq[i] * d_gwqf[w * D + i];
    for (int o = 16; o; o >>= 1) acc += __shfl_xor_sync(0xffffffffu, acc, o);
    if (l == 0) slog[w] = acc;
    __syncthreads();
    if (tid == 0) {
        float inv = 1.0f / (scale * d_wscale[0]);
        float lg[NE], mx = -1e30f;
        for (int e = 0; e < NE; e++) { lg[e] = slog[e] * inv + gb[e]; mx = fmaxf(mx, lg[e]); }
        float se = 0.f;
        for (int e = 0; e < NE; e++) { lg[e] = expf(lg[e] - mx); se += lg[e]; }
        for (int e = 0; e < NE; e++) d_gates[t * NE + e] = lg[e] / se;
    }
}

// ------- bf16 GEMM core: BM=128 BN=128 BK=64, SW128 swizzle, 3-stage cp.async (R11 champion) -------
struct Frag { float c[2][8][4]; };

__device__ __forceinline__ void g_fill(uint32_t sA, uint32_t sB, int st,
                                       const __nv_bfloat16* Ag, size_t lda,
                                       const __nv_bfloat16* Bg, size_t ldb, int k0, int tid) {
#pragma unroll
    for (int h = 0; h < 4; h++) {
        const int idx = tid + h * 256;
        const int row = idx >> 3, ch = idx & 7;
        const uint32_t off = (uint32_t)row * 128 + (uint32_t)((ch ^ (row & 7)) << 4);
        cp16(sA + (uint32_t)st * KSTG + off, Ag + (size_t)row * lda + k0 + ch * 8);
        cp16(sB + (uint32_t)st * KSTG + off, Bg + (size_t)row * ldb + k0 + ch * 8);
    }
}

__device__ __forceinline__ void g_compute(uint32_t aSt, uint32_t bSt,
                                          const uint32_t* pbA, const uint32_t* hiA,
                                          const uint32_t* pbB, const uint32_t* hiB,
                                          Frag& f) {
#pragma unroll
    for (int ks = 0; ks < 4; ks++) {
        uint32_t af[2][4], bf[8][2], t[4];
#pragma unroll
        for (int mf = 0; mf < 2; mf++)
            ldsm4(af[mf], aSt + pbA[mf] + ((((uint32_t)ks) ^ hiA[mf]) << 5));
#pragma unroll
        for (int np = 0; np < 4; np++) {
            ldsm4(t, bSt + pbB[np] + ((((uint32_t)ks) ^ hiB[np]) << 5));
            bf[np * 2][0] = t[0]; bf[np * 2][1] = t[1];
            bf[np * 2 + 1][0] = t[2]; bf[np * 2 + 1][1] = t[3];
        }
#pragma unroll
        for (int mf = 0; mf < 2; mf++)
#pragma unroll
            for (int nf = 0; nf < 8; nf++) mma16816(f.c[mf][nf], af[mf], bf[nf]);
    }
}

#define GEMM_BODY(Ag, LDA, Bg, LDB, KT)                                        \
    extern __shared__ __align__(16) char smem[];                              \
    const uint32_t sA = smem_u32(smem), sB = sA + 3 * KSTG;                   \
    const int tid = threadIdx.x;                                              \
    const int warp = tid >> 5, lane = tid & 31;                               \
    const int wm = warp >> 1, wn = warp & 1;                                  \
    const int g = lane >> 2, tq = lane & 3;                                   \
    uint32_t pbA[2], hiA[2], pbB[4], hiB[4];                                  \
    {                                                                         \
        const uint32_t hbA = ((uint32_t)lane >> 4) & 1u;                      \
        _Pragma("unroll")                                                     \
        for (int mf = 0; mf < 2; mf++) {                                      \
            const uint32_t r = (uint32_t)(wm * 32 + mf * 16) + ((uint32_t)lane & 15u); \
            pbA[mf] = r * 128u + ((hbA ^ (r & 1u)) << 4);                     \
            hiA[mf] = (r >> 1) & 3u;                                          \
        }                                                                     \
        const uint32_t hbB = ((uint32_t)lane >> 3) & 1u;                      \
        _Pragma("unroll")                                                     \
        for (int np = 0; np < 4; np++) {                                      \
            const uint32_t r = (uint32_t)(wn * 64 + np * 16) + ((uint32_t)lane & 7u) + \
                               ((((uint32_t)lane >> 4) & 1u) << 3);           \
            pbB[np] = r * 128u + ((hbB ^ (r & 1u)) << 4);                     \
            hiB[np] = (r >> 1) & 3u;                                          \
        }                                                                     \
    }                                                                         \
    Frag f;                                                                   \
    for (int i = 0; i < 2; i++)                                               \
        for (int j = 0; j < 8; j++)                                           \
            for (int k = 0; k < 4; k++) f.c[i][j][k] = 0.f;                   \
    g_fill(sA, sB, 0, Ag, LDA, Bg, LDB, 0, tid); CP_COMMIT();                 \
    g_fill(sA, sB, 1, Ag, LDA, Bg, LDB, 64, tid); CP_COMMIT();                \
    int cur = 0, nxt = 2;                                                     \
    for (int kt = 0; kt < (KT); kt++) {                                       \
        CP_WAIT1();                                                           \
        __syncthreads();                                                      \
        g_compute(sA + (uint32_t)cur * KSTG, sB + (uint32_t)cur * KSTG,       \
                  pbA, hiA, pbB, hiB, f);                                     \
        if (kt + 2 < (KT)) g_fill(sA, sB, nxt, Ag, LDA, Bg, LDB, (kt + 2) * 64, tid); \
        CP_COMMIT();                                                          \
        cur = (cur == 2) ? 0 : cur + 1;                                       \
        nxt = (nxt == 2) ? 0 : nxt + 1;                                       \
    }

// GEMM1: qx[4096,1024] @ w1q[e][H,1024]^T -> gelu -> abuf
__global__ void __launch_bounds__(256, 2) k_gemm1(const float* __restrict__ b1) {
    const int e = blockIdx.z;
    const __nv_bfloat16* Agp = d_qx + (size_t)blockIdx.x * 128 * D;
    const __nv_bfloat16* Bgp = d_w1q + ((size_t)e * H + (size_t)blockIdx.y * 128) * D;
    GEMM_BODY(Agp, D, Bgp, D, D / 64)

    const float sw1 = d_wscale[1 + e];
#pragma unroll
    for (int mf = 0; mf < 2; mf++) {
        const int r0 = blockIdx.x * 128 + wm * 32 + mf * 16 + g;
        const float i0 = 1.0f / (d_sx[r0] * sw1);
        const float i1 = 1.0f / (d_sx[r0 + 8] * sw1);
#pragma unroll
        for (int nf = 0; nf < 8; nf++) {
            const int col = blockIdx.y * 128 + wn * 64 + nf * 8 + tq * 2;
            const float bb0 = b1[e * H + col], bb1 = b1[e * H + col + 1];
            float2 o0, o1;
            o0.x = gelu_exact(f.c[mf][nf][0] * i0 + bb0);
            o0.y = gelu_exact(f.c[mf][nf][1] * i0 + bb1);
            o1.x = gelu_exact(f.c[mf][nf][2] * i1 + bb0);
            o1.y = gelu_exact(f.c[mf][nf][3] * i1 + bb1);
            *(float2*)(&d_abuf[((size_t)r0 * NE + e) * H + col]) = o0;
            *(float2*)(&d_abuf[((size_t)(r0 + 8) * NE + e) * H + col]) = o1;
        }
    }
}

// per-(token,expert) rmsnorm + quant
__global__ void __launch_bounds__(256) k_aquant() {
    const size_t r = blockIdx.x;
    const float4* a = (const float4*)(d_abuf + r * (size_t)H);
    __shared__ float wss[8], wam[8], red2[2];
    const int tid = threadIdx.x;
    float4 v[4];
    float ss = 0.f, am = 0.f;
#pragma unroll
    for (int i = 0; i < 4; i++) {
        v[i] = a[tid + i * 256];
        ss += v[i].x * v[i].x + v[i].y * v[i].y + v[i].z * v[i].z + v[i].w * v[i].w;
        am = fmaxf(am, fmaxf(fmaxf(fabsf(v[i].x), fabsf(v[i].y)),
                             fmaxf(fabsf(v[i].z), fabsf(v[i].w))));
    }
    for (int o = 16; o; o >>= 1) {
        ss += __shfl_xor_sync(0xffffffffu, ss, o);
        am = fmaxf(am, __shfl_xor_sync(0xffffffffu, am, o));
    }
    if ((tid & 31) == 0) { wss[tid >> 5] = ss; wam[tid >> 5] = am; }
    __syncthreads();
    if (tid == 0) {
        float S = 0.f, A = 0.f;
        for (int i = 0; i < 8; i++) { S += wss[i]; A = fmaxf(A, wam[i]); }
        red2[0] = S; red2[1] = A;
    }
    __syncthreads();
    const float nrm = fmaxf(sqrtf(red2[0]), 1e-12f);
    const float scale = 127.0f / fmaxf(red2[1] / nrm * 64.0f, 1e-5f);
    if (tid == 0) d_sa[r] = scale;
    const float m = 64.0f / nrm * scale;
    uint2* qo = (uint2*)(d_qa + r * (size_t)H);
#pragma unroll
    for (int i = 0; i < 4; i++) {
        qo[tid + i * 256] = packbf4(fminf(fmaxf(rintf(v[i].x * m), -128.f), 127.f),
                                    fminf(fmaxf(rintf(v[i].y * m), -128.f), 127.f),
                                    fminf(fmaxf(rintf(v[i].z * m), -128.f), 127.f),
                                    fminf(fmaxf(rintf(v[i].w * m), -128.f), 127.f));
    }
}

// GEMM2: per expert qa @ w2q^T -> gate*(c*inv+b2) -> fp16 scratch d_obuf
__global__ void __launch_bounds__(256, 2) k_gemm2(const float* __restrict__ b2) {
    const int e = blockIdx.z;
    const __nv_bfloat16* Agp = d_qa + ((size_t)blockIdx.x * 128 * NE + e) * (size_t)H;
    const __nv_bfloat16* Bgp = d_w2q + ((size_t)e * D + (size_t)blockIdx.y * 128) * H;
    GEMM_BODY(Agp, (size_t)NE * H, Bgp, H, H / 64)

    const float sw2 = d_wscale[9 + e];
#pragma unroll
    for (int mf = 0; mf < 2; mf++) {
        const int r0 = blockIdx.x * 128 + wm * 32 + mf * 16 + g;
        const float g0 = d_gates[r0 * NE + e], g1 = d_gates[(r0 + 8) * NE + e];
        const float i0 = 1.0f / (d_sa[r0 * NE + e] * sw2);
        const float i1 = 1.0f / (d_sa[(r0 + 8) * NE + e] * sw2);
#pragma unroll
        for (int nf = 0; nf < 8; nf++) {
            const int col = blockIdx.y * 128 + wn * 64 + nf * 8 + tq * 2;
            const float bb0 = b2[e * D + col], bb1 = b2[e * D + col + 1];
            __half2 h0 = __floats2half2_rn(g0 * (f.c[mf][nf][0] * i0 + bb0),
                                           g0 * (f.c[mf][nf][1] * i0 + bb1));
            __half2 h1 = __floats2half2_rn(g1 * (f.c[mf][nf][2] * i1 + bb0),
                                           g1 * (f.c[mf][nf][3] * i1 + bb1));
            *(__half2*)(&d_obuf[((size_t)r0 * NE + e) * D + col]) = h0;
            *(__half2*)(&d_obuf[((size_t)(r0 + 8) * NE + e) * D + col]) = h1;
        }
    }
}

// final reduce over experts: read fp16 scratch, accumulate fp32, write out
__global__ void __launch_bounds__(256) k_reduce(float* __restrict__ out) {
    const size_t i8 = (size_t)blockIdx.x * 256 + threadIdx.x;   // < NTOK*D/8
    const int t = (int)(i8 >> 7), d8 = (int)(i8 & 127);
    float s[8] = {0.f, 0.f, 0.f, 0.f, 0.f, 0.f, 0.f, 0.f};
#pragma unroll
    for (int e = 0; e < NE; e++) {
        const __half2* p = (const __half2*)(d_obuf + (((size_t)t * NE + e) << 10)) + d8 * 4;
#pragma unroll
        for (int j = 0; j < 4; j++) {
            float2 v = __half22float2(p[j]);
            s[j * 2] += v.x; s[j * 2 + 1] += v.y;
        }
    }
    float4* o4 = (float4*)(out + ((size_t)t << 10) + d8 * 8);
    o4[0] = make_float4(s[0], s[1], s[2], s[3]);
    o4[1] = make_float4(s[4], s[5], s[6], s[7]);
}

extern "C" void kernel_launch(void* const* d_in, const int* in_sizes, int n_in,
                              void* d_out, int out_size) {
    const float* x  = (const float*)d_in[0];
    const float* gw = (const float*)d_in[1];
    const float* gb = (const float*)d_in[2];
    const float* w1 = (const float*)d_in[3];
    const float* b1 = (const float*)d_in[4];
    const float* w2 = (const float*)d_in[5];
    const float* b2 = (const float*)d_in[6];
    float* out = (float*)d_out;

    // side-stream + events created once (first call is the uncaptured correctness
    // run, so no creation happens during graph capture; captured work is identical
    // on every call -> deterministic).
    static cudaStream_t s1 = nullptr;
    static cudaEvent_t evInit = nullptr, evW2 = nullptr;
    if (s1 == nullptr) {
        cudaStreamCreateWithFlags(&s1, cudaStreamNonBlocking);
        cudaEventCreateWithFlags(&evInit, cudaEventDisableTiming);
        cudaEventCreateWithFlags(&evW2, cudaEventDisableTiming);
    }

    cudaFuncSetAttribute(k_gemm1, cudaFuncAttributeMaxDynamicSharedMemorySize, GEMM_SMEM);
    cudaFuncSetAttribute(k_gemm2, cudaFuncAttributeMaxDynamicSharedMemorySize, GEMM_SMEM);

    k_init<<<1, 32>>>();
    cudaEventRecord(evInit, 0);

    // side stream: full w2 prep chain, joined only before gemm2
    cudaStreamWaitEvent(s1, evInit, 0);
    k_abs_sum<<<dim3(128, NE), 256, 0, s1>>>(w2, 9, (size_t)H * D);
    k_finalize<<<1, 32, 0, s1>>>(9, 17);
    k_quant_w<<<dim3(128, NE), 256, 0, s1>>>(w2, 2, 9, (size_t)H * D);
    cudaEventRecord(evW2, s1);

    // main stream: gate + w1 prep, gemm1 chain
    k_abs_sum<<<dim3(8, 1), 256>>>(gw, 0, (size_t)NE * D);
    k_abs_sum<<<dim3(128, NE), 256>>>(w1, 1, (size_t)H * D);
    k_finalize<<<1, 32>>>(0, 9);
    k_quant_gw<<<8, 256>>>(gw);
    k_quant_w<<<dim3(128, NE), 256>>>(w1, 1, 1, (size_t)H * D);
    k_xquant<<<NTOK, 256>>>(x, gb);
    k_gemm1<<<dim3(NTOK / 128, H / 128, NE), 256, GEMM_SMEM>>>(b1);
    k_aquant<<<NTOK * NE, 256>>>();

    // join side stream, then gemm2 chain
    cudaStreamWaitEvent(0, evW2, 0);
    k_gemm2<<<dim3(NTOK / 128, D / 128, NE), 256, GEMM_SMEM>>>(b2);
    k_reduce<<<(NTOK * D) / 2048, 256>>>(out);
}